// round 14
// baseline (speedup 1.0000x reference)
#include <cuda_runtime.h>

#define H    768
#define S2H  1536
#define NTOK 512      // B*S
#define SEQ  256
#define SCALE 0.70710678118654752f  // 1/sqrt(2)

// Scratch (device globals -- no allocations allowed)
__device__ float2 g_rbw2[NTOK * S2H];        // {rb' = (row_proj+b1)/sqrt2, w2' = w2/sqrt2*? see below}
__device__ float  g_cpT [2 * S2H * SEQ];     // col_proj/sqrt2, transposed: [b][c][j]

__device__ __forceinline__ float ex2f(float x) {
    float r; asm("ex2.approx.f32 %0, %1;" : "=f"(r) : "f"(x)); return r;
}
__device__ __forceinline__ float rcpf(float x) {
    float r; asm("rcp.approx.f32 %0, %1;" : "=f"(r) : "f"(x)); return r;
}

// ---------------- start / end logits: warp per token ----------------
__global__ __launch_bounds__(128) void se_logits_kernel(
    const float* __restrict__ hidden,
    const float* __restrict__ w_start, const float* __restrict__ b_start,
    const float* __restrict__ w_end,   const float* __restrict__ b_end,
    float* __restrict__ out)
{
    int warp = threadIdx.x >> 5, lane = threadIdx.x & 31;
    int tok  = blockIdx.x * 4 + warp;
    if (tok >= NTOK) return;
    const float* hp = hidden + tok * H;
    float as = 0.f, ae = 0.f;
    #pragma unroll
    for (int h = lane; h < H; h += 32) {
        float x = hp[h];
        as = fmaf(x, w_start[h], as);
        ae = fmaf(x, w_end[h],   ae);
    }
    #pragma unroll
    for (int o = 16; o; o >>= 1) {
        as += __shfl_xor_sync(0xffffffffu, as, o);
        ae += __shfl_xor_sync(0xffffffffu, ae, o);
    }
    if (lane == 0) {
        out[tok]        = as + b_start[0];
        out[NTOK + tok] = ae + b_end[0];
    }
}

// ---------------- projection GEMM: [512,768] x [768,3072] ----------------
// n' in [0,1536)    -> rb  (weights w1 rows [0,768),   +b1, *SCALE, interleave w2*SCALE)
// n' in [1536,3072) -> cpT (weights w1 rows [768,1536), *SCALE, transposed store)
#define BK 16
__global__ __launch_bounds__(256) void proj_gemm_kernel(
    const float* __restrict__ hidden, const float* __restrict__ w1,
    const float* __restrict__ b1,     const float* __restrict__ w2)
{
    __shared__ float As[BK][68];   // [k][m], padded to 68 (16B aligned, reduced conflicts)
    __shared__ float Bs[BK][64];   // [k][n]

    int t  = threadIdx.x;
    int bn = blockIdx.x * 64;      // 0..3071
    int bm = blockIdx.y * 64;      // 0..511
    bool half = (bn >= S2H);
    int col0  = half ? (bn - S2H) : bn;
    const float* Ap = hidden + bm * H;
    const float* Bp = w1 + (half ? H : 0) * S2H + col0;

    int ar = t >> 2,  ac = (t & 3)  * 4;   // A staging: row, k-offset
    int br = t >> 4,  bc = (t & 15) * 4;   // B staging: k-row, n-offset
    int tx = t & 15,  ty = t >> 4;         // micro-tile coords

    float c[4][4] = {};
    for (int kt = 0; kt < H; kt += BK) {
        float4 av = *(const float4*)(Ap + ar * H + kt + ac);
        float4 bv = *(const float4*)(Bp + (size_t)(kt + br) * S2H + bc);
        As[ac+0][ar] = av.x; As[ac+1][ar] = av.y;
        As[ac+2][ar] = av.z; As[ac+3][ar] = av.w;
        *(float4*)&Bs[br][bc] = bv;
        __syncthreads();
        #pragma unroll
        for (int k = 0; k < BK; k++) {
            float4 a = *(const float4*)&As[k][ty * 4];
            float4 b = *(const float4*)&Bs[k][tx * 4];
            c[0][0]=fmaf(a.x,b.x,c[0][0]); c[0][1]=fmaf(a.x,b.y,c[0][1]);
            c[0][2]=fmaf(a.x,b.z,c[0][2]); c[0][3]=fmaf(a.x,b.w,c[0][3]);
            c[1][0]=fmaf(a.y,b.x,c[1][0]); c[1][1]=fmaf(a.y,b.y,c[1][1]);
            c[1][2]=fmaf(a.y,b.z,c[1][2]); c[1][3]=fmaf(a.y,b.w,c[1][3]);
            c[2][0]=fmaf(a.z,b.x,c[2][0]); c[2][1]=fmaf(a.z,b.y,c[2][1]);
            c[2][2]=fmaf(a.z,b.z,c[2][2]); c[2][3]=fmaf(a.z,b.w,c[2][3]);
            c[3][0]=fmaf(a.w,b.x,c[3][0]); c[3][1]=fmaf(a.w,b.y,c[3][1]);
            c[3][2]=fmaf(a.w,b.z,c[3][2]); c[3][3]=fmaf(a.w,b.w,c[3][3]);
        }
        __syncthreads();
    }

    if (!half) {
        #pragma unroll
        for (int i = 0; i < 4; i++) {
            int m = bm + ty * 4 + i;
            #pragma unroll
            for (int j = 0; j < 4; j++) {
                int col = col0 + tx * 4 + j;
                float v = (c[i][j] + b1[col]) * SCALE;
                g_rbw2[m * S2H + col] = make_float2(v, w2[col] * SCALE);
            }
        }
    } else {
        #pragma unroll
        for (int i = 0; i < 4; i++) {
            int m = bm + ty * 4 + i;           // m = b*256 + j_token
            int bb = m >> 8, jt = m & 255;
            #pragma unroll
            for (int j = 0; j < 4; j++) {
                int col = col0 + tx * 4 + j;
                g_cpT[((size_t)bb * S2H + col) * SEQ + jt] = c[i][j] * SCALE;
            }
        }
    }
}

// ---------------- match logits: one thread per (i,j) output ----------------
// out[i,j] = sum_c gelu(rb[i,c]+cp[j,c]) * w2[c] + b2, with u = pre/sqrt2 pre-scaled.
// Branchless exact erf (A&S 7.1.26, |err|<=1.5e-7):
//   erfc(|u|) = (a1 t + .. + a5 t^5) e^{-u^2}, t = 1/(1+p|u|)
//   u*(1+erf(u)) = (u+|u|) - |u|*erfc(|u|)        (valid for both signs, no select)
__global__ __launch_bounds__(128) void match_kernel(
    const float* __restrict__ b2v, float* __restrict__ out_match)
{
    int j  = blockIdx.x * 128 + threadIdx.x;   // 0..255
    int ig = blockIdx.y;                        // b*256 + i
    int b  = ig >> 8;

    const float2* __restrict__ rw = g_rbw2 + (size_t)ig * S2H;
    const float*  __restrict__ cp = g_cpT + (size_t)b * S2H * SEQ + j;

    const float KL2E = -1.4426950408889634f;   // -log2(e)
    const float P  = 0.3275911f;
    const float A1 = 0.254829592f,  A2 = -0.284496736f, A3 = 1.421413741f;
    const float A4 = -1.453152027f, A5 = 1.061405429f;

    float acc = 0.f;
    #pragma unroll 8
    for (int c = 0; c < S2H; c++) {
        float2 rbw = rw[c];                    // broadcast, L1-hot
        float  cpv = cp[(size_t)c * SEQ];      // coalesced
        float u  = rbw.x + cpv;                // = pre/sqrt2
        float au = fabsf(u);
        float e  = ex2f((u * KL2E) * u);       // exp(-u^2)
        float tt = rcpf(fmaf(P, au, 1.0f));
        float r  = fmaf(A5, tt, A4);
        r = fmaf(r, tt, A3);
        r = fmaf(r, tt, A2);
        r = fmaf(r, tt, A1);
        float q = (r * tt) * e;                // erfc(|u|)
        float g = fmaf(-au, q, u + au);        // u*(1+erf(u))
        acc = fmaf(g, rbw.y, acc);             // * w2/sqrt2  (gelu = 0.5*x*(1+erf) = u/sqrt2*(1+erf)*... folded)
    }
    out_match[(size_t)ig * SEQ + j] = acc + b2v[0];
}

extern "C" void kernel_launch(void* const* d_in, const int* in_sizes, int n_in,
                              void* d_out, int out_size)
{
    const float* hidden  = (const float*)d_in[0];
    const float* w_start = (const float*)d_in[1];
    const float* b_start = (const float*)d_in[2];
    const float* w_end   = (const float*)d_in[3];
    const float* b_end   = (const float*)d_in[4];
    const float* w1      = (const float*)d_in[5];
    const float* b1      = (const float*)d_in[6];
    const float* w2      = (const float*)d_in[7];
    const float* b2      = (const float*)d_in[8];
    float* out = (float*)d_out;   // [512 start | 512 end | 2*256*256 match]

    se_logits_kernel<<<128, 128>>>(hidden, w_start, b_start, w_end, b_end, out);
    proj_gemm_kernel<<<dim3(48, 8), 256>>>(hidden, w1, b1, w2);
    match_kernel<<<dim3(2, 512), 128>>>(b2, out + 2 * NTOK);
}

// round 15
// speedup vs baseline: 1.0015x; 1.0015x over previous
#include <cuda_runtime.h>

#define H    768
#define S2H  1536
#define NTOK 512      // B*S
#define SEQ  256
#define SCALE 0.70710678118654752f  // 1/sqrt(2)

// Scratch (device globals -- no allocations allowed)
__device__ float2 g_rbw2[NTOK * S2H];        // {rb' = (row_proj+b1)/sqrt2, w2' = w2/sqrt2*? see below}
__device__ float  g_cpT [2 * S2H * SEQ];     // col_proj/sqrt2, transposed: [b][c][j]

__device__ __forceinline__ float ex2f(float x) {
    float r; asm("ex2.approx.f32 %0, %1;" : "=f"(r) : "f"(x)); return r;
}
__device__ __forceinline__ float rcpf(float x) {
    float r; asm("rcp.approx.f32 %0, %1;" : "=f"(r) : "f"(x)); return r;
}

// ---------------- start / end logits: warp per token ----------------
__global__ __launch_bounds__(128) void se_logits_kernel(
    const float* __restrict__ hidden,
    const float* __restrict__ w_start, const float* __restrict__ b_start,
    const float* __restrict__ w_end,   const float* __restrict__ b_end,
    float* __restrict__ out)
{
    int warp = threadIdx.x >> 5, lane = threadIdx.x & 31;
    int tok  = blockIdx.x * 4 + warp;
    if (tok >= NTOK) return;
    const float* hp = hidden + tok * H;
    float as = 0.f, ae = 0.f;
    #pragma unroll
    for (int h = lane; h < H; h += 32) {
        float x = hp[h];
        as = fmaf(x, w_start[h], as);
        ae = fmaf(x, w_end[h],   ae);
    }
    #pragma unroll
    for (int o = 16; o; o >>= 1) {
        as += __shfl_xor_sync(0xffffffffu, as, o);
        ae += __shfl_xor_sync(0xffffffffu, ae, o);
    }
    if (lane == 0) {
        out[tok]        = as + b_start[0];
        out[NTOK + tok] = ae + b_end[0];
    }
}

// ---------------- projection GEMM: [512,768] x [768,3072] ----------------
// n' in [0,1536)    -> rb  (weights w1 rows [0,768),   +b1, *SCALE, interleave w2*SCALE)
// n' in [1536,3072) -> cpT (weights w1 rows [768,1536), *SCALE, transposed store)
#define BK 16
__global__ __launch_bounds__(256) void proj_gemm_kernel(
    const float* __restrict__ hidden, const float* __restrict__ w1,
    const float* __restrict__ b1,     const float* __restrict__ w2)
{
    __shared__ float As[BK][68];   // [k][m], padded to 68 (16B aligned, reduced conflicts)
    __shared__ float Bs[BK][64];   // [k][n]

    int t  = threadIdx.x;
    int bn = blockIdx.x * 64;      // 0..3071
    int bm = blockIdx.y * 64;      // 0..511
    bool half = (bn >= S2H);
    int col0  = half ? (bn - S2H) : bn;
    const float* Ap = hidden + bm * H;
    const float* Bp = w1 + (half ? H : 0) * S2H + col0;

    int ar = t >> 2,  ac = (t & 3)  * 4;   // A staging: row, k-offset
    int br = t >> 4,  bc = (t & 15) * 4;   // B staging: k-row, n-offset
    int tx = t & 15,  ty = t >> 4;         // micro-tile coords

    float c[4][4] = {};
    for (int kt = 0; kt < H; kt += BK) {
        float4 av = *(const float4*)(Ap + ar * H + kt + ac);
        float4 bv = *(const float4*)(Bp + (size_t)(kt + br) * S2H + bc);
        As[ac+0][ar] = av.x; As[ac+1][ar] = av.y;
        As[ac+2][ar] = av.z; As[ac+3][ar] = av.w;
        *(float4*)&Bs[br][bc] = bv;
        __syncthreads();
        #pragma unroll
        for (int k = 0; k < BK; k++) {
            float4 a = *(const float4*)&As[k][ty * 4];
            float4 b = *(const float4*)&Bs[k][tx * 4];
            c[0][0]=fmaf(a.x,b.x,c[0][0]); c[0][1]=fmaf(a.x,b.y,c[0][1]);
            c[0][2]=fmaf(a.x,b.z,c[0][2]); c[0][3]=fmaf(a.x,b.w,c[0][3]);
            c[1][0]=fmaf(a.y,b.x,c[1][0]); c[1][1]=fmaf(a.y,b.y,c[1][1]);
            c[1][2]=fmaf(a.y,b.z,c[1][2]); c[1][3]=fmaf(a.y,b.w,c[1][3]);
            c[2][0]=fmaf(a.z,b.x,c[2][0]); c[2][1]=fmaf(a.z,b.y,c[2][1]);
            c[2][2]=fmaf(a.z,b.z,c[2][2]); c[2][3]=fmaf(a.z,b.w,c[2][3]);
            c[3][0]=fmaf(a.w,b.x,c[3][0]); c[3][1]=fmaf(a.w,b.y,c[3][1]);
            c[3][2]=fmaf(a.w,b.z,c[3][2]); c[3][3]=fmaf(a.w,b.w,c[3][3]);
        }
        __syncthreads();
    }

    if (!half) {
        #pragma unroll
        for (int i = 0; i < 4; i++) {
            int m = bm + ty * 4 + i;
            #pragma unroll
            for (int j = 0; j < 4; j++) {
                int col = col0 + tx * 4 + j;
                float v = (c[i][j] + b1[col]) * SCALE;
                g_rbw2[m * S2H + col] = make_float2(v, w2[col] * SCALE);
            }
        }
    } else {
        #pragma unroll
        for (int i = 0; i < 4; i++) {
            int m = bm + ty * 4 + i;           // m = b*256 + j_token
            int bb = m >> 8, jt = m & 255;
            #pragma unroll
            for (int j = 0; j < 4; j++) {
                int col = col0 + tx * 4 + j;
                g_cpT[((size_t)bb * S2H + col) * SEQ + jt] = c[i][j] * SCALE;
            }
        }
    }
}

// ---------------- match logits: one thread per (i,j) output ----------------
// out[i,j] = sum_c gelu(rb[i,c]+cp[j,c]) * w2[c] + b2, with u = pre/sqrt2 pre-scaled.
// Branchless exact erf (A&S 7.1.26, |err|<=1.5e-7):
//   erfc(|u|) = (a1 t + .. + a5 t^5) e^{-u^2}, t = 1/(1+p|u|)
//   u*(1+erf(u)) = (u+|u|) - |u|*erfc(|u|)        (valid for both signs, no select)
__global__ __launch_bounds__(128) void match_kernel(
    const float* __restrict__ b2v, float* __restrict__ out_match)
{
    int j  = blockIdx.x * 128 + threadIdx.x;   // 0..255
    int ig = blockIdx.y;                        // b*256 + i
    int b  = ig >> 8;

    const float2* __restrict__ rw = g_rbw2 + (size_t)ig * S2H;
    const float*  __restrict__ cp = g_cpT + (size_t)b * S2H * SEQ + j;

    const float KL2E = -1.4426950408889634f;   // -log2(e)
    const float P  = 0.3275911f;
    const float A1 = 0.254829592f,  A2 = -0.284496736f, A3 = 1.421413741f;
    const float A4 = -1.453152027f, A5 = 1.061405429f;

    float acc = 0.f;
    #pragma unroll 8
    for (int c = 0; c < S2H; c++) {
        float2 rbw = rw[c];                    // broadcast, L1-hot
        float  cpv = cp[(size_t)c * SEQ];      // coalesced
        float u  = rbw.x + cpv;                // = pre/sqrt2
        float au = fabsf(u);
        float e  = ex2f((u * KL2E) * u);       // exp(-u^2)
        float tt = rcpf(fmaf(P, au, 1.0f));
        float r  = fmaf(A5, tt, A4);
        r = fmaf(r, tt, A3);
        r = fmaf(r, tt, A2);
        r = fmaf(r, tt, A1);
        float q = (r * tt) * e;                // erfc(|u|)
        float g = fmaf(-au, q, u + au);        // u*(1+erf(u))
        acc = fmaf(g, rbw.y, acc);             // * w2/sqrt2  (gelu = 0.5*x*(1+erf) = u/sqrt2*(1+erf)*... folded)
    }
    out_match[(size_t)ig * SEQ + j] = acc + b2v[0];
}

extern "C" void kernel_launch(void* const* d_in, const int* in_sizes, int n_in,
                              void* d_out, int out_size)
{
    const float* hidden  = (const float*)d_in[0];
    const float* w_start = (const float*)d_in[1];
    const float* b_start = (const float*)d_in[2];
    const float* w_end   = (const float*)d_in[3];
    const float* b_end   = (const float*)d_in[4];
    const float* w1      = (const float*)d_in[5];
    const float* b1      = (const float*)d_in[6];
    const float* w2      = (const float*)d_in[7];
    const float* b2      = (const float*)d_in[8];
    float* out = (float*)d_out;   // [512 start | 512 end | 2*256*256 match]

    se_logits_kernel<<<128, 128>>>(hidden, w_start, b_start, w_end, b_end, out);
    proj_gemm_kernel<<<dim3(48, 8), 256>>>(hidden, w1, b1, w2);
    match_kernel<<<dim3(2, 512), 128>>>(b2, out + 2 * NTOK);
}

// round 16
// speedup vs baseline: 1.0020x; 1.0004x over previous
#include <cuda_runtime.h>

#define H    768
#define S2H  1536
#define NTOK 512      // B*S
#define SEQ  256
#define SCALE 0.70710678118654752f  // 1/sqrt(2)

// Scratch (device globals -- no allocations allowed)
__device__ float2 g_rbw2[NTOK * S2H];        // {rb' = (row_proj+b1)/sqrt2, w2' = w2/sqrt2*? see below}
__device__ float  g_cpT [2 * S2H * SEQ];     // col_proj/sqrt2, transposed: [b][c][j]

__device__ __forceinline__ float ex2f(float x) {
    float r; asm("ex2.approx.f32 %0, %1;" : "=f"(r) : "f"(x)); return r;
}
__device__ __forceinline__ float rcpf(float x) {
    float r; asm("rcp.approx.f32 %0, %1;" : "=f"(r) : "f"(x)); return r;
}

// ---------------- start / end logits: warp per token ----------------
__global__ __launch_bounds__(128) void se_logits_kernel(
    const float* __restrict__ hidden,
    const float* __restrict__ w_start, const float* __restrict__ b_start,
    const float* __restrict__ w_end,   const float* __restrict__ b_end,
    float* __restrict__ out)
{
    int warp = threadIdx.x >> 5, lane = threadIdx.x & 31;
    int tok  = blockIdx.x * 4 + warp;
    if (tok >= NTOK) return;
    const float* hp = hidden + tok * H;
    float as = 0.f, ae = 0.f;
    #pragma unroll
    for (int h = lane; h < H; h += 32) {
        float x = hp[h];
        as = fmaf(x, w_start[h], as);
        ae = fmaf(x, w_end[h],   ae);
    }
    #pragma unroll
    for (int o = 16; o; o >>= 1) {
        as += __shfl_xor_sync(0xffffffffu, as, o);
        ae += __shfl_xor_sync(0xffffffffu, ae, o);
    }
    if (lane == 0) {
        out[tok]        = as + b_start[0];
        out[NTOK + tok] = ae + b_end[0];
    }
}

// ---------------- projection GEMM: [512,768] x [768,3072] ----------------
// n' in [0,1536)    -> rb  (weights w1 rows [0,768),   +b1, *SCALE, interleave w2*SCALE)
// n' in [1536,3072) -> cpT (weights w1 rows [768,1536), *SCALE, transposed store)
#define BK 16
__global__ __launch_bounds__(256) void proj_gemm_kernel(
    const float* __restrict__ hidden, const float* __restrict__ w1,
    const float* __restrict__ b1,     const float* __restrict__ w2)
{
    __shared__ float As[BK][68];   // [k][m], padded to 68 (16B aligned, reduced conflicts)
    __shared__ float Bs[BK][64];   // [k][n]

    int t  = threadIdx.x;
    int bn = blockIdx.x * 64;      // 0..3071
    int bm = blockIdx.y * 64;      // 0..511
    bool half = (bn >= S2H);
    int col0  = half ? (bn - S2H) : bn;
    const float* Ap = hidden + bm * H;
    const float* Bp = w1 + (half ? H : 0) * S2H + col0;

    int ar = t >> 2,  ac = (t & 3)  * 4;   // A staging: row, k-offset
    int br = t >> 4,  bc = (t & 15) * 4;   // B staging: k-row, n-offset
    int tx = t & 15,  ty = t >> 4;         // micro-tile coords

    float c[4][4] = {};
    for (int kt = 0; kt < H; kt += BK) {
        float4 av = *(const float4*)(Ap + ar * H + kt + ac);
        float4 bv = *(const float4*)(Bp + (size_t)(kt + br) * S2H + bc);
        As[ac+0][ar] = av.x; As[ac+1][ar] = av.y;
        As[ac+2][ar] = av.z; As[ac+3][ar] = av.w;
        *(float4*)&Bs[br][bc] = bv;
        __syncthreads();
        #pragma unroll
        for (int k = 0; k < BK; k++) {
            float4 a = *(const float4*)&As[k][ty * 4];
            float4 b = *(const float4*)&Bs[k][tx * 4];
            c[0][0]=fmaf(a.x,b.x,c[0][0]); c[0][1]=fmaf(a.x,b.y,c[0][1]);
            c[0][2]=fmaf(a.x,b.z,c[0][2]); c[0][3]=fmaf(a.x,b.w,c[0][3]);
            c[1][0]=fmaf(a.y,b.x,c[1][0]); c[1][1]=fmaf(a.y,b.y,c[1][1]);
            c[1][2]=fmaf(a.y,b.z,c[1][2]); c[1][3]=fmaf(a.y,b.w,c[1][3]);
            c[2][0]=fmaf(a.z,b.x,c[2][0]); c[2][1]=fmaf(a.z,b.y,c[2][1]);
            c[2][2]=fmaf(a.z,b.z,c[2][2]); c[2][3]=fmaf(a.z,b.w,c[2][3]);
            c[3][0]=fmaf(a.w,b.x,c[3][0]); c[3][1]=fmaf(a.w,b.y,c[3][1]);
            c[3][2]=fmaf(a.w,b.z,c[3][2]); c[3][3]=fmaf(a.w,b.w,c[3][3]);
        }
        __syncthreads();
    }

    if (!half) {
        #pragma unroll
        for (int i = 0; i < 4; i++) {
            int m = bm + ty * 4 + i;
            #pragma unroll
            for (int j = 0; j < 4; j++) {
                int col = col0 + tx * 4 + j;
                float v = (c[i][j] + b1[col]) * SCALE;
                g_rbw2[m * S2H + col] = make_float2(v, w2[col] * SCALE);
            }
        }
    } else {
        #pragma unroll
        for (int i = 0; i < 4; i++) {
            int m = bm + ty * 4 + i;           // m = b*256 + j_token
            int bb = m >> 8, jt = m & 255;
            #pragma unroll
            for (int j = 0; j < 4; j++) {
                int col = col0 + tx * 4 + j;
                g_cpT[((size_t)bb * S2H + col) * SEQ + jt] = c[i][j] * SCALE;
            }
        }
    }
}

// ---------------- match logits: one thread per (i,j) output ----------------
// out[i,j] = sum_c gelu(rb[i,c]+cp[j,c]) * w2[c] + b2, with u = pre/sqrt2 pre-scaled.
// Branchless exact erf (A&S 7.1.26, |err|<=1.5e-7):
//   erfc(|u|) = (a1 t + .. + a5 t^5) e^{-u^2}, t = 1/(1+p|u|)
//   u*(1+erf(u)) = (u+|u|) - |u|*erfc(|u|)        (valid for both signs, no select)
__global__ __launch_bounds__(128) void match_kernel(
    const float* __restrict__ b2v, float* __restrict__ out_match)
{
    int j  = blockIdx.x * 128 + threadIdx.x;   // 0..255
    int ig = blockIdx.y;                        // b*256 + i
    int b  = ig >> 8;

    const float2* __restrict__ rw = g_rbw2 + (size_t)ig * S2H;
    const float*  __restrict__ cp = g_cpT + (size_t)b * S2H * SEQ + j;

    const float KL2E = -1.4426950408889634f;   // -log2(e)
    const float P  = 0.3275911f;
    const float A1 = 0.254829592f,  A2 = -0.284496736f, A3 = 1.421413741f;
    const float A4 = -1.453152027f, A5 = 1.061405429f;

    float acc = 0.f;
    #pragma unroll 8
    for (int c = 0; c < S2H; c++) {
        float2 rbw = rw[c];                    // broadcast, L1-hot
        float  cpv = cp[(size_t)c * SEQ];      // coalesced
        float u  = rbw.x + cpv;                // = pre/sqrt2
        float au = fabsf(u);
        float e  = ex2f((u * KL2E) * u);       // exp(-u^2)
        float tt = rcpf(fmaf(P, au, 1.0f));
        float r  = fmaf(A5, tt, A4);
        r = fmaf(r, tt, A3);
        r = fmaf(r, tt, A2);
        r = fmaf(r, tt, A1);
        float q = (r * tt) * e;                // erfc(|u|)
        float g = fmaf(-au, q, u + au);        // u*(1+erf(u))
        acc = fmaf(g, rbw.y, acc);             // * w2/sqrt2  (gelu = 0.5*x*(1+erf) = u/sqrt2*(1+erf)*... folded)
    }
    out_match[(size_t)ig * SEQ + j] = acc + b2v[0];
}

extern "C" void kernel_launch(void* const* d_in, const int* in_sizes, int n_in,
                              void* d_out, int out_size)
{
    const float* hidden  = (const float*)d_in[0];
    const float* w_start = (const float*)d_in[1];
    const float* b_start = (const float*)d_in[2];
    const float* w_end   = (const float*)d_in[3];
    const float* b_end   = (const float*)d_in[4];
    const float* w1      = (const float*)d_in[5];
    const float* b1      = (const float*)d_in[6];
    const float* w2      = (const float*)d_in[7];
    const float* b2      = (const float*)d_in[8];
    float* out = (float*)d_out;   // [512 start | 512 end | 2*256*256 match]

    se_logits_kernel<<<128, 128>>>(hidden, w_start, b_start, w_end, b_end, out);
    proj_gemm_kernel<<<dim3(48, 8), 256>>>(hidden, w1, b1, w2);
    match_kernel<<<dim3(2, 512), 128>>>(b2, out + 2 * NTOK);
}

// round 17
// speedup vs baseline: 1.0037x; 1.0018x over previous
#include <cuda_runtime.h>

#define H    768
#define S2H  1536
#define NTOK 512      // B*S
#define SEQ  256
#define SCALE 0.70710678118654752f  // 1/sqrt(2)

typedef unsigned long long u64;

// Scratch (device globals -- no allocations allowed)
__device__ float g_rb [NTOK * S2H];        // (row_proj + b1) / sqrt2
__device__ float g_cpT[2 * S2H * SEQ];     // col_proj / sqrt2, transposed: [b][c][j]

// ---------------- f32x2 packed helpers ----------------
__device__ __forceinline__ u64 pk2(float a, float b) {
    u64 r; asm("mov.b64 %0, {%1, %2};" : "=l"(r) : "f"(a), "f"(b)); return r;
}
__device__ __forceinline__ void upk2(float& a, float& b, u64 v) {
    asm("mov.b64 {%0, %1}, %2;" : "=f"(a), "=f"(b) : "l"(v));
}
__device__ __forceinline__ u64 fma2(u64 a, u64 b, u64 c) {
    u64 r; asm("fma.rn.f32x2 %0, %1, %2, %3;" : "=l"(r) : "l"(a), "l"(b), "l"(c)); return r;
}
__device__ __forceinline__ u64 add2(u64 a, u64 b) {
    u64 r; asm("add.rn.f32x2 %0, %1, %2;" : "=l"(r) : "l"(a), "l"(b)); return r;
}
__device__ __forceinline__ u64 mul2(u64 a, u64 b) {
    u64 r; asm("mul.rn.f32x2 %0, %1, %2;" : "=l"(r) : "l"(a), "l"(b)); return r;
}
__device__ __forceinline__ u64 and64(u64 a, u64 m) {
    u64 r; asm("and.b64 %0, %1, %2;" : "=l"(r) : "l"(a), "l"(m)); return r;
}
__device__ __forceinline__ float ex2f(float x) {
    float r; asm("ex2.approx.f32 %0, %1;" : "=f"(r) : "f"(x)); return r;
}
__device__ __forceinline__ float rcpf(float x) {
    float r; asm("rcp.approx.f32 %0, %1;" : "=f"(r) : "f"(x)); return r;
}

// ---------------- start / end logits: warp per token ----------------
__global__ __launch_bounds__(128) void se_logits_kernel(
    const float* __restrict__ hidden,
    const float* __restrict__ w_start, const float* __restrict__ b_start,
    const float* __restrict__ w_end,   const float* __restrict__ b_end,
    float* __restrict__ out)
{
    int warp = threadIdx.x >> 5, lane = threadIdx.x & 31;
    int tok  = blockIdx.x * 4 + warp;
    if (tok >= NTOK) return;
    const float* hp = hidden + tok * H;
    float as = 0.f, ae = 0.f;
    #pragma unroll
    for (int h = lane; h < H; h += 32) {
        float x = hp[h];
        as = fmaf(x, w_start[h], as);
        ae = fmaf(x, w_end[h],   ae);
    }
    #pragma unroll
    for (int o = 16; o; o >>= 1) {
        as += __shfl_xor_sync(0xffffffffu, as, o);
        ae += __shfl_xor_sync(0xffffffffu, ae, o);
    }
    if (lane == 0) {
        out[tok]        = as + b_start[0];
        out[NTOK + tok] = ae + b_end[0];
    }
}

// ---------------- projection GEMM: [512,768] x [768,3072] ----------------
// n' in [0,1536)    -> g_rb  (weights w1 rows [0,768),   +b1, *SCALE)
// n' in [1536,3072) -> g_cpT (weights w1 rows [768,1536), *SCALE, transposed store)
#define BK 16
__global__ __launch_bounds__(256) void proj_gemm_kernel(
    const float* __restrict__ hidden, const float* __restrict__ w1,
    const float* __restrict__ b1)
{
    __shared__ float As[BK][68];   // [k][m]
    __shared__ float Bs[BK][64];   // [k][n]

    int t  = threadIdx.x;
    int bn = blockIdx.x * 64;      // 0..3071
    int bm = blockIdx.y * 64;      // 0..511
    bool half = (bn >= S2H);
    int col0  = half ? (bn - S2H) : bn;
    const float* Ap = hidden + bm * H;
    const float* Bp = w1 + (half ? H : 0) * S2H + col0;

    int ar = t >> 2,  ac = (t & 3)  * 4;
    int br = t >> 4,  bc = (t & 15) * 4;
    int tx = t & 15,  ty = t >> 4;

    float c[4][4] = {};
    for (int kt = 0; kt < H; kt += BK) {
        float4 av = *(const float4*)(Ap + ar * H + kt + ac);
        float4 bv = *(const float4*)(Bp + (size_t)(kt + br) * S2H + bc);
        As[ac+0][ar] = av.x; As[ac+1][ar] = av.y;
        As[ac+2][ar] = av.z; As[ac+3][ar] = av.w;
        *(float4*)&Bs[br][bc] = bv;
        __syncthreads();
        #pragma unroll
        for (int k = 0; k < BK; k++) {
            float4 a = *(const float4*)&As[k][ty * 4];
            float4 b = *(const float4*)&Bs[k][tx * 4];
            c[0][0]=fmaf(a.x,b.x,c[0][0]); c[0][1]=fmaf(a.x,b.y,c[0][1]);
            c[0][2]=fmaf(a.x,b.z,c[0][2]); c[0][3]=fmaf(a.x,b.w,c[0][3]);
            c[1][0]=fmaf(a.y,b.x,c[1][0]); c[1][1]=fmaf(a.y,b.y,c[1][1]);
            c[1][2]=fmaf(a.y,b.z,c[1][2]); c[1][3]=fmaf(a.y,b.w,c[1][3]);
            c[2][0]=fmaf(a.z,b.x,c[2][0]); c[2][1]=fmaf(a.z,b.y,c[2][1]);
            c[2][2]=fmaf(a.z,b.z,c[2][2]); c[2][3]=fmaf(a.z,b.w,c[2][3]);
            c[3][0]=fmaf(a.w,b.x,c[3][0]); c[3][1]=fmaf(a.w,b.y,c[3][1]);
            c[3][2]=fmaf(a.w,b.z,c[3][2]); c[3][3]=fmaf(a.w,b.w,c[3][3]);
        }
        __syncthreads();
    }

    if (!half) {
        int col = col0 + tx * 4;
        float4 bb = *(const float4*)(b1 + col);
        #pragma unroll
        for (int i = 0; i < 4; i++) {
            int m = bm + ty * 4 + i;
            float4 v;
            v.x = (c[i][0] + bb.x) * SCALE;
            v.y = (c[i][1] + bb.y) * SCALE;
            v.z = (c[i][2] + bb.z) * SCALE;
            v.w = (c[i][3] + bb.w) * SCALE;
            *(float4*)&g_rb[(size_t)m * S2H + col] = v;
        }
    } else {
        #pragma unroll
        for (int i = 0; i < 4; i++) {
            int m = bm + ty * 4 + i;           // m = b*256 + j_token
            int bb = m >> 8, jt = m & 255;
            #pragma unroll
            for (int j = 0; j < 4; j++) {
                int col = col0 + tx * 4 + j;
                g_cpT[((size_t)bb * S2H + col) * SEQ + jt] = c[i][j] * SCALE;
            }
        }
    }
}

// ---------------- match logits: one thread per (i,j), channel-PAIR packed ----------------
// out[i,j] = SCALE * sum_c g(u_c) * w2[c] + b2,  u = (rb+cp) already /sqrt2,
// g(u) = u*(1+erf(u)) = (u+|u|) - |u|*erfc(|u|).
// A&S 7.1.26 with NEGATED coefficients so the poly yields -erfc directly:
// q = r*t*e^{-u^2} = -erfc(|u|); g = fma(|u|, q, u+|u|).
// All fma-class ops are packed f32x2 over channel pairs (c even/odd);
// rb and w2 pairs load as natural 64-bit register pairs.
__global__ __launch_bounds__(512) void match_kernel(
    const float* __restrict__ w2, const float* __restrict__ b2v,
    float* __restrict__ out_match)
{
    int ig = blockIdx.y * 2 + (threadIdx.x >> 8);   // token index (i-pair per block)
    int j  = threadIdx.x & 255;
    int b  = ig >> 8;                               // never straddles within a block

    const float* __restrict__ rb = g_rb + (size_t)ig * S2H;
    const float* __restrict__ cp = g_cpT + (size_t)b * S2H * SEQ + j;

    const float KL2E = -1.4426950408889634f;        // -log2(e)
    const u64 KL2 = pk2(KL2E, KL2E);
    const u64 P2  = pk2(0.3275911f, 0.3275911f);
    const u64 ONE = pk2(1.0f, 1.0f);
    const u64 A1n = pk2(-0.254829592f, -0.254829592f);
    const u64 A2n = pk2( 0.284496736f,  0.284496736f);
    const u64 A3n = pk2(-1.421413741f, -1.421413741f);
    const u64 A4n = pk2( 1.453152027f,  1.453152027f);
    const u64 A5n = pk2(-1.061405429f, -1.061405429f);
    const u64 MASK = 0x7FFFFFFF7FFFFFFFull;

    u64 acc = 0;                                    // {0.f, 0.f}
    #pragma unroll 2
    for (int c = 0; c < S2H; c += 2) {
        u64 rb2 = *(const u64*)(rb + c);            // LDG.64, broadcast (L1-hot)
        u64 w22 = *(const u64*)(w2 + c);            // LDG.64, broadcast (L1-hot)
        float cpa = cp[(size_t)c * SEQ];            // coalesced
        float cpb = cp[(size_t)(c + 1) * SEQ];      // coalesced
        u64 u  = add2(rb2, pk2(cpa, cpb));          // = pre/sqrt2  (packed pair)
        u64 au = and64(u, MASK);                    // |u| (alu pipe)
        u64 x  = mul2(mul2(u, KL2), u);             // -u^2*log2(e)
        float xa, xb; upk2(xa, xb, x);
        u64 e2 = pk2(ex2f(xa), ex2f(xb));           // exp(-u^2)
        u64 d  = fma2(P2, au, ONE);
        float da, db; upk2(da, db, d);
        u64 t2 = pk2(rcpf(da), rcpf(db));           // 1/(1+p|u|)
        u64 r  = fma2(A5n, t2, A4n);
        r = fma2(r, t2, A3n);
        r = fma2(r, t2, A2n);
        r = fma2(r, t2, A1n);
        u64 q  = mul2(mul2(r, t2), e2);             // -erfc(|u|)
        u64 g  = fma2(au, q, add2(u, au));          // u*(1+erf(u))
        acc = fma2(g, w22, acc);
    }
    float sa, sb; upk2(sa, sb, acc);
    out_match[(size_t)ig * SEQ + j] = fmaf(sa + sb, SCALE, b2v[0]);
}

extern "C" void kernel_launch(void* const* d_in, const int* in_sizes, int n_in,
                              void* d_out, int out_size)
{
    const float* hidden  = (const float*)d_in[0];
    const float* w_start = (const float*)d_in[1];
    const float* b_start = (const float*)d_in[2];
    const float* w_end   = (const float*)d_in[3];
    const float* b_end   = (const float*)d_in[4];
    const float* w1      = (const float*)d_in[5];
    const float* b1      = (const float*)d_in[6];
    const float* w2      = (const float*)d_in[7];
    const float* b2      = (const float*)d_in[8];
    float* out = (float*)d_out;   // [512 start | 512 end | 2*256*256 match]

    se_logits_kernel<<<128, 128>>>(hidden, w_start, b_start, w_end, b_end, out);
    proj_gemm_kernel<<<dim3(48, 8), 256>>>(hidden, w1, b1);
    match_kernel<<<dim3(1, 256), 512>>>(w2, b2, out + 2 * NTOK);
}